// round 3
// baseline (speedup 1.0000x reference)
#include <cuda_runtime.h>
#include <cuda_fp16.h>
#include <cstdint>

#define NN 100000
#define DD 64
#define EE 400000
#define TT 5

// Scratch (device globals — no allocation allowed)
__device__ __half g_Ph[(size_t)2 * TT * NN * DD];  // fp16 tables, 128MB
__device__ int   g_counts[TT * NN];

// ---------------------------------------------------------------- utilities
__device__ __forceinline__ uint32_t f2tf32(float f) {
    uint32_t r;
    asm("cvt.rna.tf32.f32 %0, %1;" : "=r"(r) : "f"(f));
    return r;
}
__device__ __forceinline__ void mma_tf32(float* c, uint32_t a0, uint32_t a1,
                                         uint32_t a2, uint32_t a3,
                                         uint32_t b0, uint32_t b1) {
    asm("mma.sync.aligned.m16n8k8.row.col.f32.tf32.tf32.f32 "
        "{%0,%1,%2,%3}, {%4,%5,%6,%7}, {%8,%9}, {%0,%1,%2,%3};"
        : "+f"(c[0]), "+f"(c[1]), "+f"(c[2]), "+f"(c[3])
        : "r"(a0), "r"(a1), "r"(a2), "r"(a3), "r"(b0), "r"(b1));
}

// ---------------------------------------------------------------- kernels
__global__ void zero_kernel(float* out) {
    int i = blockIdx.x * blockDim.x + threadIdx.x;
    if (i < NN * DD) out[i] = 0.0f;
    if (i < TT * NN) g_counts[i] = 0;
}

__global__ void count_kernel(const int* __restrict__ edges) {
    int i = blockIdx.x * blockDim.x + threadIdx.x;
    if (i >= TT * EE) return;
    int t = i / EE;
    int e = i - t * EE;
    int src = edges[(size_t)t * 2 * EE + e];
    atomicAdd(&g_counts[t * NN + src], 1);
}

// P[y][n][c] = sum_k x[n][k] * W[t][half*64+k][c],  y = t*2+half.
// tf32 mma.sync m16n8k8; bias folded into the even (src) half; fp16 output.
// Block: 64 nodes x 64 cols, 128 threads (4 warps, each 32 rows x 32 cols).
// k-permutation within each k8 tile (j<->2j, j+4<->2j+1) makes every
// fragment load a contiguous conflict-free LDS.64 from stride-72 smem.
__global__ __launch_bounds__(128) void gemm_kernel(const float* __restrict__ x,
                                                   const float* __restrict__ W,
                                                   const float* __restrict__ bvec) {
    __shared__ uint32_t xs[64 * 72];  // x tile, tf32 bits, [row][k] stride 72
    __shared__ uint32_t ws[64 * 72];  // W^T tile, tf32 bits, [col][k] stride 72
    const int tid = threadIdx.x;
    const int y = blockIdx.y;         // t*2+half, 0..9
    const int n0 = blockIdx.x * 64;

    // Stage W slab (4096 floats), transposed to [c][k]
#pragma unroll
    for (int i = 0; i < 32; i++) {
        int idx = tid + i * 128;
        float v = W[(size_t)y * 4096 + idx];
        ws[(idx & 63) * 72 + (idx >> 6)] = f2tf32(v);
    }
    // Stage x tile: thread owns half a row
    {
        int r = tid >> 1, s = tid & 1;
        int n = n0 + r;
        const float4* xg = (const float4*)(x + (size_t)n * 64 + s * 32);
#pragma unroll
        for (int i = 0; i < 8; i++) {
            float4 v = (n < NN) ? xg[i] : make_float4(0.f, 0.f, 0.f, 0.f);
            uint32_t* p = &xs[r * 72 + s * 32 + i * 4];
            p[0] = f2tf32(v.x); p[1] = f2tf32(v.y);
            p[2] = f2tf32(v.z); p[3] = f2tf32(v.w);
        }
    }
    __syncthreads();

    const int lane = tid & 31, w = tid >> 5;
    const int mbase = (w & 1) * 32;    // row base within the 64-row tile
    const int cbase = (w >> 1) * 32;   // col base within the 64-col tile
    const int qr = lane >> 2, qj = lane & 3;

    float acc[2][4][4];
#pragma unroll
    for (int m = 0; m < 2; m++)
#pragma unroll
        for (int n = 0; n < 4; n++)
#pragma unroll
            for (int f = 0; f < 4; f++) acc[m][n][f] = 0.0f;

#pragma unroll
    for (int kt = 0; kt < 8; kt++) {
        const int kk = kt * 8 + 2 * qj;
        uint2 A0a = *(const uint2*)&xs[(mbase + qr) * 72 + kk];
        uint2 A0b = *(const uint2*)&xs[(mbase + qr + 8) * 72 + kk];
        uint2 A1a = *(const uint2*)&xs[(mbase + 16 + qr) * 72 + kk];
        uint2 A1b = *(const uint2*)&xs[(mbase + 24 + qr) * 72 + kk];
#pragma unroll
        for (int nt = 0; nt < 4; nt++) {
            uint2 B = *(const uint2*)&ws[(cbase + nt * 8 + qr) * 72 + kk];
            mma_tf32(acc[0][nt], A0a.x, A0b.x, A0a.y, A0b.y, B.x, B.y);
            mma_tf32(acc[1][nt], A1a.x, A1b.x, A1a.y, A1b.y, B.x, B.y);
        }
    }

    // Bias (src half only): this lane's 2 cols per n-tile
    float2 bb[4];
    if ((y & 1) == 0) {
        const int t = y >> 1;
#pragma unroll
        for (int nt = 0; nt < 4; nt++)
            bb[nt] = *(const float2*)&bvec[t * DD + cbase + nt * 8 + 2 * qj];
    } else {
#pragma unroll
        for (int nt = 0; nt < 4; nt++) bb[nt] = make_float2(0.f, 0.f);
    }

    // Bounce fragments through smem (reuse xs) for coalesced fp16 stores.
    __syncthreads();
    __half* hs = (__half*)xs;   // [64 rows][72 halves]
#pragma unroll
    for (int m = 0; m < 2; m++) {
#pragma unroll
        for (int nt = 0; nt < 4; nt++) {
            int col = cbase + nt * 8 + 2 * qj;
            int r0 = mbase + m * 16 + qr;
            *(__half2*)&hs[r0 * 72 + col] =
                __floats2half2_rn(acc[m][nt][0] + bb[nt].x, acc[m][nt][1] + bb[nt].y);
            *(__half2*)&hs[(r0 + 8) * 72 + col] =
                __floats2half2_rn(acc[m][nt][2] + bb[nt].x, acc[m][nt][3] + bb[nt].y);
        }
    }
    __syncthreads();

    // Coalesced write-out: thread owns half a row (32 halves = 64B)
    {
        int r = tid >> 1, s = tid & 1;
        int n = n0 + r;
        if (n < NN) {
            uint2* dst = (uint2*)&g_Ph[(((size_t)y * NN) + n) * 64 + s * 32];
            const uint2* srcp = (const uint2*)&hs[r * 72 + s * 32];
#pragma unroll
            for (int i = 0; i < 4; i++) {
                uint2 v0 = srcp[2 * i];
                uint2 v1 = srcp[2 * i + 1];
                dst[2 * i] = v0;
                dst[2 * i + 1] = v1;
            }
        }
    }
}

// Edge aggregation: 8 lanes (8 fp16 cols = 16B each) per edge-instance.
// out[src] += (softmax(ea)[t]/max(count,1)) * relu(A'[t][src] + C[t][dst])
__global__ __launch_bounds__(256) void edge_kernel(const int* __restrict__ edges,
                                                   const float* __restrict__ ea,
                                                   float* __restrict__ out) {
    __shared__ float wsm[TT];
    if (threadIdx.x == 0) {
        float m = -1e30f;
#pragma unroll
        for (int t = 0; t < TT; t++) m = fmaxf(m, ea[t]);
        float e[TT], ssum = 0.0f;
#pragma unroll
        for (int t = 0; t < TT; t++) { e[t] = expf(ea[t] - m); ssum += e[t]; }
#pragma unroll
        for (int t = 0; t < TT; t++) wsm[t] = e[t] / ssum;
    }
    __syncthreads();

    int gtid = blockIdx.x * blockDim.x + threadIdx.x;
    int grp = gtid >> 3;
    int lane = gtid & 7;
    if (grp >= TT * EE) return;
    int t = grp / EE;
    int e = grp - t * EE;

    const int* eb = edges + (size_t)t * 2 * EE;
    int src = eb[e];
    int dst = eb[EE + e];

    int cnt = g_counts[t * NN + src];
    float s = __fdividef(wsm[t], (float)(cnt > 1 ? cnt : 1));

    const uint4* P4 = (const uint4*)g_Ph;   // 8 uint4 per 64-col row
    uint4 av = P4[((size_t)(2 * t) * NN + src) * 8 + lane];
    uint4 cv = P4[((size_t)(2 * t + 1) * NN + dst) * 8 + lane];

    float v[8];
    {
        const __half2* ah = (const __half2*)&av;
        const __half2* ch = (const __half2*)&cv;
#pragma unroll
        for (int j = 0; j < 4; j++) {
            float2 fa = __half22float2(ah[j]);
            float2 fc = __half22float2(ch[j]);
            v[2 * j]     = fmaxf(fa.x + fc.x, 0.0f) * s;
            v[2 * j + 1] = fmaxf(fa.y + fc.y, 0.0f) * s;
        }
    }

    float* dp = out + ((size_t)src * 64 + lane * 8);
    asm volatile("red.global.add.v4.f32 [%0], {%1, %2, %3, %4};"
                 :: "l"(dp), "f"(v[0]), "f"(v[1]), "f"(v[2]), "f"(v[3])
                 : "memory");
    asm volatile("red.global.add.v4.f32 [%0], {%1, %2, %3, %4};"
                 :: "l"(dp + 4), "f"(v[4]), "f"(v[5]), "f"(v[6]), "f"(v[7])
                 : "memory");
}

// ---------------------------------------------------------------- launcher
extern "C" void kernel_launch(void* const* d_in, const int* in_sizes, int n_in,
                              void* d_out, int out_size) {
    const float* x = nullptr;
    const float* W = nullptr;
    const float* b = nullptr;
    const float* ea = nullptr;
    const int* edges = nullptr;

    for (int i = 0; i < n_in; i++) {
        switch (in_sizes[i]) {
            case NN * DD:          x     = (const float*)d_in[i]; break;  // 6,400,000
            case TT * 2 * DD * DD: W     = (const float*)d_in[i]; break;  // 40,960
            case TT * DD:          b     = (const float*)d_in[i]; break;  // 320
            case TT:               ea    = (const float*)d_in[i]; break;  // 5
            case TT * 2 * EE:      edges = (const int*)d_in[i];   break;  // 4,000,000
        }
    }

    float* out = (float*)d_out;

    zero_kernel<<<(NN * DD + 255) / 256, 256>>>(out);
    count_kernel<<<(TT * EE + 255) / 256, 256>>>(edges);
    gemm_kernel<<<dim3((NN + 63) / 64, 2 * TT), 128>>>(x, W, b);
    edge_kernel<<<(TT * EE * 8 + 255) / 256, 256>>>(edges, ea, out);
}